// round 17
// baseline (speedup 1.0000x reference)
#include <cuda_runtime.h>
#include <cuda_fp16.h>
#include <cstdint>
#include <math.h>

// Problem constants: B=4, H=W=64 -> N=4096 tokens, C=256, GROUPS=8
#define B_ 4
#define NTOK 4096
#define C_ 256
#define GRP 8
#define CG 32
#define ROWS_TOT (B_*NTOK)   // 16384

// ---------------- scratch (device globals) ------------------------------------
__device__ float2 g_part[32*8];           // groupnorm partial (sum, sumsq)
__device__ float  g_b3[768];              // packed bq|bk|bv
__device__ __half g_xnh[ROWS_TOT*C_];     // normalized input fp16 (GEMM operand + residual)
__device__ __half g_qk[ROWS_TOT*512];     // q (cols 0-255), k (cols 256-511)
__device__ __half g_vT[ROWS_TOT*C_];      // V transposed: [C_][ROWS_TOT]
__device__ __half g_o[ROWS_TOT*C_];       // attn output (pre-projection)
__device__ __half g_wt[4*C_*C_];          // transposed weights: wtq wtk wtv wtp
__device__ __half g_attn[(size_t)B_*NTOK*NTOK];  // unnormalized exp(QK^T/16), 134 MB

// ---------------- helpers -------------------------------------------------------
__device__ __forceinline__ uint32_t smem_u32(const void* p) {
    uint32_t a;
    asm("{ .reg .u64 t; cvta.to.shared.u64 t, %1; cvt.u32.u64 %0, t; }" : "=r"(a) : "l"(p));
    return a;
}
__device__ __forceinline__ void cp16(uint32_t dst, const void* src) {
    asm volatile("cp.async.cg.shared.global [%0], [%1], 16;" :: "r"(dst), "l"(src));
}
__device__ __forceinline__ void ldsm4(uint32_t& r0, uint32_t& r1, uint32_t& r2,
                                      uint32_t& r3, uint32_t addr) {
    asm volatile("ldmatrix.sync.aligned.m8n8.x4.shared.b16 {%0,%1,%2,%3}, [%4];"
                 : "=r"(r0), "=r"(r1), "=r"(r2), "=r"(r3) : "r"(addr));
}

// fp16 m16n8k16 MMA, fp32 accumulate.
__device__ __forceinline__ void mma16816(float* d, const uint32_t* a, const uint32_t* b) {
    asm volatile(
        "mma.sync.aligned.m16n8k16.row.col.f32.f16.f16.f32 "
        "{%0,%1,%2,%3}, {%4,%5,%6,%7}, {%8,%9}, {%0,%1,%2,%3};"
        : "+f"(d[0]), "+f"(d[1]), "+f"(d[2]), "+f"(d[3])
        : "r"(a[0]), "r"(a[1]), "r"(a[2]), "r"(a[3]), "r"(b[0]), "r"(b[1]));
}
__device__ __forceinline__ float h2sum(uint32_t u) {
    __half2 h = *(__half2*)&u;
    float2 f = __half22float2(h);
    return f.x + f.y;
}

// ---------------- prep: GN partial stats + weight transposes + bias pack --------
__global__ __launch_bounds__(256) void prep(
    const float* __restrict__ x,
    const float* __restrict__ W0, const float* __restrict__ W1,
    const float* __restrict__ W2, const float* __restrict__ W3,
    const float* __restrict__ bq, const float* __restrict__ bk,
    const float* __restrict__ bv)
{
    if (blockIdx.y < 8) {
        int bg = blockIdx.x, slice = blockIdx.y;
        int b = bg >> 3, g = bg & 7;
        const float* xb = x + (size_t)b * NTOK * C_ + g * CG + (size_t)slice * 512 * C_;
        float s = 0.f, ss = 0.f;
        for (int i = threadIdx.x; i < 512 * CG; i += 256) {
            int n = i >> 5, c = i & 31;
            float v = __ldg(&xb[(size_t)n * C_ + c]);
            s += v; ss += v * v;
        }
        __shared__ float sh1[256], sh2[256];
        int t = threadIdx.x;
        sh1[t] = s; sh2[t] = ss;
        __syncthreads();
        for (int o = 128; o > 0; o >>= 1) {
            if (t < o) { sh1[t] += sh1[t + o]; sh2[t] += sh2[t + o]; }
            __syncthreads();
        }
        if (t == 0) g_part[bg * 8 + slice] = make_float2(sh1[0], sh2[0]);
    } else {
        int idx = blockIdx.x + 32 * (blockIdx.y - 8);
        __shared__ float tsm[32][33];
        int tx = threadIdx.x & 31, ty = threadIdx.x >> 5;
        for (int tt = 0; tt < 4; tt++) {
            int tile = idx * 4 + tt;
            int w = tile >> 6, rem = tile & 63;
            int c0 = (rem & 7) * 32, k0 = (rem >> 3) * 32;
            const float* W = (w == 0) ? W0 : (w == 1) ? W1 : (w == 2) ? W2 : W3;
            __half* Wt = g_wt + (size_t)w * C_ * C_;
            __syncthreads();
#pragma unroll
            for (int j = 0; j < 4; j++)
                tsm[ty + 8 * j][tx] = W[(size_t)(k0 + ty + 8 * j) * C_ + c0 + tx];
            __syncthreads();
#pragma unroll
            for (int j = 0; j < 4; j++)
                Wt[(size_t)(c0 + ty + 8 * j) * C_ + k0 + tx] = __float2half(tsm[tx][ty + 8 * j]);
        }
        if (blockIdx.x == 31 && blockIdx.y == 9) {
            for (int i = threadIdx.x; i < 768; i += 256) {
                float v = (i < 256) ? bq[i] : (i < 512) ? bk[i - 256] : bv[i - 512];
                g_b3[i] = v;
            }
        }
    }
}

// ---------------- GroupNorm apply: combine + normalize (fp16 out) ---------------
__global__ __launch_bounds__(256) void gn_norm(const float* __restrict__ x,
                                               const float* __restrict__ gamma,
                                               const float* __restrict__ beta) {
    __shared__ float smean[32], srstd[32];
    if (threadIdx.x < 32) {
        int bg = threadIdx.x;
        float s = 0.f, ss = 0.f;
#pragma unroll
        for (int i = 0; i < 8; i++) {
            float2 p = g_part[bg * 8 + i];
            s += p.x; ss += p.y;
        }
        float inv = 1.f / (float)(NTOK * CG);
        float m = s * inv;
        float var = ss * inv - m * m;
        smean[bg] = m;
        srstd[bg] = rsqrtf(var + 1e-3f);
    }
    __syncthreads();
    size_t i4 = (size_t)blockIdx.x * blockDim.x + threadIdx.x;
    size_t i = i4 * 4;
    int c = (int)(i & (C_ - 1));
    size_t row = i >> 8;
    int b = (int)(row >> 12);
    int bg = b * GRP + (c >> 5);
    float m = smean[bg], r = srstd[bg];
    float4 xv = ((const float4*)x)[i4];
    float4 gv = *(const float4*)(gamma + c);
    float4 bv = *(const float4*)(beta + c);
    float4 o;
    o.x = (xv.x - m) * r * gv.x + bv.x;
    o.y = (xv.y - m) * r * gv.y + bv.y;
    o.z = (xv.z - m) * r * gv.z + bv.z;
    o.w = (xv.w - m) * r * gv.w + bv.w;
    __half2 h01 = __floats2half2_rn(o.x, o.y);
    __half2 h23 = __floats2half2_rn(o.z, o.w);
    uint2 hp = make_uint2(*(uint32_t*)&h01, *(uint32_t*)&h23);
    ((uint2*)g_xnh)[i4] = hp;   // GEMM operand AND residual (fp16)
}

// ---------------- fp16 mma.sync TN GEMM: D = A[M,K] @ B[N,K]^T ------------------
// 128x128 CTA tile, 8 warps of 64x32, kc=64 halves, 3-stage cp.async ring,
// ldmatrix fragment loads. 96 KB smem -> 2 CTAs/SM.
#define NSTAGE 3
#define STAGE_BYTES 16384            // 128x64 halves
#define SM_B (NSTAGE*STAGE_BYTES)
#define GSMEM (2*NSTAGE*STAGE_BYTES) // 96 KB

template<bool BIAS, bool RES, bool EXP, bool NORM, bool OUTF32, bool QKVE>
__global__ __launch_bounds__(256, 2) void gemm_h(
    const __half* __restrict__ A, const __half* __restrict__ B,
    const float* __restrict__ bias, const __half* __restrict__ res,
    __half* __restrict__ vtp,
    void* __restrict__ Cv, int lda, int ldb, int ldc, int K,
    long sA, long sB, long sC, float scale)
{
    extern __shared__ char smem[];
    const uint32_t sb = smem_u32(smem);
    const int tid = threadIdx.x, wid = tid >> 5, lane = tid & 31;
    const int gid = lane >> 2, tig = lane & 3;
    const int row0 = blockIdx.y * 128, col0 = blockIdx.x * 128;
    const int wm = (wid & 1) * 64, wn = (wid >> 1) * 32;
    const __half* Ab = A + (size_t)blockIdx.z * sA;
    const __half* Bb = B + (size_t)blockIdx.z * sB;

    float acc[4][4][4];
#pragma unroll
    for (int i = 0; i < 4; i++)
#pragma unroll
        for (int j = 0; j < 4; j++)
#pragma unroll
            for (int e = 0; e < 4; e++) acc[i][j][e] = 0.f;

    float rowpart[4][2];
    if (NORM) {
#pragma unroll
        for (int i = 0; i < 4; i++) { rowpart[i][0] = 0.f; rowpart[i][1] = 0.f; }
    }

    const int nk = K >> 6;   // 64 halves per chunk

    const int amr = wm + (lane & 15);
    const int ahv = lane >> 4;
    const int ar7 = amr & 7;
    const int bnr = wn + (lane & 7) + ((lane >> 4) << 3);
    const int bhv = (lane >> 3) & 1;
    const int br7 = bnr & 7;

    auto load_chunk = [&](int ck, int st) {
        uint32_t ab = sb + st * STAGE_BYTES;
        uint32_t bbs = sb + SM_B + st * STAGE_BYTES;
        int k0 = ck * 64;
#pragma unroll
        for (int j = 0; j < 4; j++) {
            int s = tid + 256 * j;
            int r = s >> 3, g = s & 7;
            uint32_t off = (uint32_t)(r * 128 + ((g ^ (r & 7)) << 4));
            cp16(ab + off, Ab + (size_t)(row0 + r) * lda + k0 + g * 8);
            cp16(bbs + off, Bb + (size_t)(col0 + r) * ldb + k0 + g * 8);
        }
    };

#pragma unroll
    for (int p = 0; p < NSTAGE - 1; p++) {
        if (p < nk) load_chunk(p, p);
        asm volatile("cp.async.commit_group;" ::: "memory");
    }

    int st = 0, stl = NSTAGE - 1;
    for (int i = 0; i < nk; i++) {
        asm volatile("cp.async.wait_group %0;" :: "n"(NSTAGE - 2) : "memory");
        __syncthreads();
        if (i + NSTAGE - 1 < nk) load_chunk(i + NSTAGE - 1, stl);
        asm volatile("cp.async.commit_group;" ::: "memory");

        uint32_t as = sb + st * STAGE_BYTES + (uint32_t)(amr * 128);
        uint32_t bs = sb + SM_B + st * STAGE_BYTES + (uint32_t)(bnr * 128);
#pragma unroll
        for (int k16 = 0; k16 < 4; k16++) {
            uint32_t af[4][4], bf[4][2];
            uint32_t aswz = (uint32_t)(((k16 * 2 + ahv) ^ ar7) << 4);
            uint32_t bswz = (uint32_t)(((k16 * 2 + bhv) ^ br7) << 4);
#pragma unroll
            for (int mi = 0; mi < 4; mi++)
                ldsm4(af[mi][0], af[mi][1], af[mi][2], af[mi][3],
                      as + aswz + mi * 2048);
            ldsm4(bf[0][0], bf[0][1], bf[1][0], bf[1][1], bs + bswz);
            ldsm4(bf[2][0], bf[2][1], bf[3][0], bf[3][1], bs + bswz + 2048);
#pragma unroll
            for (int mi = 0; mi < 4; mi++)
#pragma unroll
                for (int ni = 0; ni < 4; ni++)
                    mma16816(acc[mi][ni], af[mi], bf[ni]);
            if (NORM) {
#pragma unroll
                for (int mi = 0; mi < 4; mi++) {
                    rowpart[mi][0] += h2sum(af[mi][0]) + h2sum(af[mi][2]);
                    rowpart[mi][1] += h2sum(af[mi][1]) + h2sum(af[mi][3]);
                }
            }
        }
        st = (st + 1 == NSTAGE) ? 0 : st + 1;
        stl = (stl + 1 == NSTAGE) ? 0 : stl + 1;
    }

    if (NORM) {
#pragma unroll
        for (int mi = 0; mi < 4; mi++)
#pragma unroll
            for (int h = 0; h < 2; h++) {
                float s = rowpart[mi][h];
                s += __shfl_xor_sync(0xffffffffu, s, 1);
                s += __shfl_xor_sync(0xffffffffu, s, 2);
                rowpart[mi][h] = 1.f / s;
            }
    }

    // epilogue: c0,c1 at (row gid, col tig*2,+1); c2,c3 at row+8
#pragma unroll
    for (int mi = 0; mi < 4; mi++) {
#pragma unroll
        for (int ni = 0; ni < 4; ni++) {
            int r0 = row0 + wm + mi * 16 + gid;
            int c = col0 + wn + ni * 8 + tig * 2;
#pragma unroll
            for (int h = 0; h < 2; h++) {
                int r = r0 + h * 8;
                float v0 = acc[mi][ni][h * 2 + 0] * scale;
                float v1 = acc[mi][ni][h * 2 + 1] * scale;
                if (NORM) {
                    float inv = rowpart[mi][h];
                    v0 *= inv; v1 *= inv;
                }
                if (EXP) { v0 = __expf(v0); v1 = __expf(v1); }
                if (BIAS) {
                    float2 bb = *(const float2*)(bias + c);
                    v0 += bb.x; v1 += bb.y;
                }
                if (RES) {
                    __half2 rh = *(const __half2*)(res + (size_t)r * ldc + c);
                    float2 rr = __half22float2(rh);
                    v0 += rr.x; v1 += rr.y;
                }
                if (QKVE) {
                    // cols 0-511: q|k row-major (ldc=512); cols 512-767: vT
                    if (c < 512) {
                        __half* Cb = (__half*)Cv;
                        __half2 hv = __floats2half2_rn(v0, v1);
                        *(__half2*)(Cb + (size_t)r * 512 + c) = hv;
                    } else {
                        vtp[(size_t)(c - 512) * ROWS_TOT + r] = __float2half(v0);
                        vtp[(size_t)(c - 511) * ROWS_TOT + r] = __float2half(v1);
                    }
                } else if (OUTF32) {
                    float* Cb = (float*)Cv + (size_t)blockIdx.z * sC;
                    *(float2*)(Cb + (size_t)r * ldc + c) = make_float2(v0, v1);
                } else {
                    __half* Cb = (__half*)Cv + (size_t)blockIdx.z * sC;
                    __half2 hv = __floats2half2_rn(v0, v1);
                    *(__half2*)(Cb + (size_t)r * ldc + c) = hv;
                }
            }
        }
    }
}

// -------------------------------- launch ---------------------------------------
extern "C" void kernel_launch(void* const* d_in, const int* in_sizes, int n_in,
                              void* d_out, int out_size) {
    const float* x     = (const float*)d_in[0];
    const float* gamma = (const float*)d_in[1];
    const float* beta  = (const float*)d_in[2];
    const float* Wq    = (const float*)d_in[3];
    const float* bq    = (const float*)d_in[4];
    const float* Wk    = (const float*)d_in[5];
    const float* bk    = (const float*)d_in[6];
    const float* Wv    = (const float*)d_in[7];
    const float* bv    = (const float*)d_in[8];
    const float* Wp    = (const float*)d_in[9];
    const float* bp    = (const float*)d_in[10];
    float* out = (float*)d_out;
    (void)in_sizes; (void)n_in; (void)out_size;

    float* b3;
    __half *xnh, *qk, *vT, *o, *attn, *wt;
    cudaGetSymbolAddress((void**)&b3,   g_b3);
    cudaGetSymbolAddress((void**)&xnh,  g_xnh);
    cudaGetSymbolAddress((void**)&qk,   g_qk);
    cudaGetSymbolAddress((void**)&vT,   g_vT);
    cudaGetSymbolAddress((void**)&o,    g_o);
    cudaGetSymbolAddress((void**)&attn, g_attn);
    cudaGetSymbolAddress((void**)&wt,   g_wt);
    __half* wtqkv = wt;               // wtq|wtk|wtv: 768 rows of 256
    __half* wtp   = wt + 3*C_*C_;

    // Host-side stream/event objects. Created once on the first (uncaptured,
    // correctness) call; reused during graph capture via the standard event
    // fork/join pattern, which capture supports. No device memory involved.
    static cudaStream_t s2 = nullptr;
    static cudaEvent_t evFork = nullptr, evJoin = nullptr, evQ[B_] = {};
    if (!s2) {
        cudaStreamCreateWithFlags(&s2, cudaStreamNonBlocking);
        cudaEventCreateWithFlags(&evFork, cudaEventDisableTiming);
        cudaEventCreateWithFlags(&evJoin, cudaEventDisableTiming);
        for (int b = 0; b < B_; b++)
            cudaEventCreateWithFlags(&evQ[b], cudaEventDisableTiming);
    }

    cudaFuncSetAttribute(gemm_h<true,false,false,false,false,true>,  cudaFuncAttributeMaxDynamicSharedMemorySize, GSMEM);
    cudaFuncSetAttribute(gemm_h<false,false,true,false,false,false>, cudaFuncAttributeMaxDynamicSharedMemorySize, GSMEM);
    cudaFuncSetAttribute(gemm_h<false,false,false,true,false,false>, cudaFuncAttributeMaxDynamicSharedMemorySize, GSMEM);
    cudaFuncSetAttribute(gemm_h<true,true,false,false,true,false>,   cudaFuncAttributeMaxDynamicSharedMemorySize, GSMEM);

    // ---- main stream: prep, gn_norm, qkvProj ----
    dim3 gp(32, 10);
    prep<<<gp, 256>>>(x, Wq, Wk, Wv, Wp, bq, bk, bv);
    gn_norm<<<(ROWS_TOT * C_ / 4) / 256, 256>>>(x, gamma, beta);

    dim3 gQKV(6, 128, 1);
    gemm_h<true,false,false,false,false,true><<<gQKV, 256, GSMEM>>>(
        xnh, wtqkv, b3, nullptr, vT, qk, C_, C_, 512, C_, 0, 0, 0, 1.f);

    cudaEventRecord(evFork, 0);
    cudaStreamWaitEvent(s2, evFork, 0);

    // ---- main stream: QK^T per batch; side stream: PV(b) after QKT(b) ----
    dim3 gS(32, 32, 1);
    dim3 gAV(2, 32, 1);
    for (int b = 0; b < B_; b++) {
        const __half* qkb = qk + (size_t)b * NTOK * 512;
        __half* attnb = attn + (size_t)b * NTOK * NTOK;
        gemm_h<false,false,true,false,false,false><<<gS, 256, GSMEM>>>(
            qkb, qkb + 256, nullptr, nullptr, nullptr, attnb,
            512, 512, NTOK, C_, 0, 0, 0, 0.0625f);
        cudaEventRecord(evQ[b], 0);
    }
    for (int b = 0; b < B_; b++) {
        cudaStreamWaitEvent(s2, evQ[b], 0);
        const __half* attnb = attn + (size_t)b * NTOK * NTOK;
        gemm_h<false,false,false,true,false,false><<<gAV, 256, GSMEM, s2>>>(
            attnb, vT + (size_t)b * NTOK, nullptr, nullptr, nullptr,
            o + (size_t)b * NTOK * C_, NTOK, ROWS_TOT, C_, NTOK, 0, 0, 0, 1.f);
    }

    // ---- side stream: final projection + bias + fp16 residual -> d_out ----
    dim3 gP(2, 128, 1);
    gemm_h<true,true,false,false,true,false><<<gP, 256, GSMEM, s2>>>(
        o, wtp, bp, xnh, nullptr, out, C_, C_, C_, C_, 0, 0, 0, 1.f);

    cudaEventRecord(evJoin, s2);
    cudaStreamWaitEvent(0, evJoin, 0);
}